// round 14
// baseline (speedup 1.0000x reference)
#include <cuda_runtime.h>
#include <cuda_fp16.h>
#include <cstdint>

// B=8192, D=128. sim = (Z Z^T)/0.1 with masked logsumexps -> scalar mean.
// fp16 GEMM (fp16 accum) on mma.sync, K=128, exp2-folded.
// Upper-triangle 128x128 tiles; dual-anchor packed-f32x2 epilogue.
// THIS ROUND: smem diet -> 4 CTAs/SM (54KB/CTA): A staged once full-K
// (256B rows), B single-buffered in two K=64 chunks. regs capped 64.
#define BDIM 8192
#define DDIM 128
#define TM   128
#define TN   128
#define KC   64
#define NSEG 128
#define NT   64
#define TTHRESH 365

__device__ __half g_za[BDIM * DDIM];          // 2MB: fp16(14.427*z)
__device__ __half g_zb[BDIM * DDIM];          // 2MB: fp16(z)
__device__ float2 g_part[BDIM * NSEG];        // 8MB
__device__ float  g_bsum[BDIM / 256];
__device__ float  g_bcnt[BDIM / 256];
__device__ int    g_ticket = 0;

// ---------------- PTX helpers ----------------
__device__ __forceinline__ uint32_t smem_u32(const void* p) {
    uint32_t a;
    asm("{ .reg .u64 t; cvta.to.shared.u64 t, %1; cvt.u32.u64 %0, t; }" : "=r"(a) : "l"(p));
    return a;
}
__device__ __forceinline__ void cp16(uint32_t dst, const void* src) {
    asm volatile("cp.async.cg.shared.global [%0], [%1], 16;" :: "r"(dst), "l"(src));
}
__device__ __forceinline__ void cp_commit() {
    asm volatile("cp.async.commit_group;" ::: "memory");
}
template <int N> __device__ __forceinline__ void cp_wait() {
    asm volatile("cp.async.wait_group %0;" :: "n"(N) : "memory");
}
__device__ __forceinline__ void ldsm4(uint32_t& r0, uint32_t& r1, uint32_t& r2,
                                      uint32_t& r3, uint32_t addr) {
    asm volatile("ldmatrix.sync.aligned.m8n8.x4.shared.b16 {%0,%1,%2,%3}, [%4];"
                 : "=r"(r0), "=r"(r1), "=r"(r2), "=r"(r3) : "r"(addr));
}
__device__ __forceinline__ void mma16816h(uint32_t& d0, uint32_t& d1,
                                          uint32_t a0, uint32_t a1, uint32_t a2,
                                          uint32_t a3, uint32_t b0, uint32_t b1) {
    asm volatile(
        "mma.sync.aligned.m16n8k16.row.col.f16.f16.f16.f16 "
        "{%0,%1}, {%2,%3,%4,%5}, {%6,%7}, {%0,%1};"
        : "+r"(d0), "+r"(d1)
        : "r"(a0), "r"(a1), "r"(a2), "r"(a3), "r"(b0), "r"(b1));
}
__device__ __forceinline__ uint32_t ex2h2(uint32_t x) {
    uint32_t r;
    asm("ex2.approx.f16x2 %0, %1;" : "=r"(r) : "r"(x));
    return r;
}
__device__ __forceinline__ unsigned long long pk2(float lo, float hi) {
    unsigned long long r;
    asm("mov.b64 %0, {%1, %2};" : "=l"(r) : "f"(lo), "f"(hi));
    return r;
}
__device__ __forceinline__ void unpk2(unsigned long long v, float& lo, float& hi) {
    asm("mov.b64 {%0, %1}, %2;" : "=f"(lo), "=f"(hi) : "l"(v));
}
__device__ __forceinline__ unsigned long long add2(unsigned long long a,
                                                   unsigned long long b) {
    unsigned long long d;
    asm("add.rn.f32x2 %0, %1, %2;" : "=l"(d) : "l"(a), "l"(b));
    return d;
}

// SMEM: A full-K 32K | B chunk 16K | colp 4K | ti/cenR/tj/cenC 4x512 = 54K
#define SM_A    0
#define SM_B    32768
#define SM_COLP 49152
#define SM_TI   53248
#define SM_CENR 53760
#define SM_TJ   54272
#define SM_CENC 54784
#define SMEM_TOTAL 55296

// No-op kernel: keeps ncu's profiled launch (#4) on main_kernel.
__global__ void nop_kernel() {}

// ---- Kernel 1: normalize + fp16 encode (exp2 scale folded into A) ----
__global__ void norm_kernel(const float* __restrict__ emb) {
    int row  = blockIdx.x * 8 + threadIdx.y;
    int lane = threadIdx.x;
    float4 v = ((const float4*)(emb + (size_t)row * DDIM))[lane];
    float ss = v.x * v.x + v.y * v.y + v.z * v.z + v.w * v.w;
    #pragma unroll
    for (int o = 16; o; o >>= 1) ss += __shfl_xor_sync(0xFFFFFFFFu, ss, o);
    float inv = rsqrtf(fmaxf(ss, 1e-24f));
    inv = inv * (1.5f - 0.5f * ss * inv * inv);
    const float SC = 14.426950408889634f;   // 10 / ln(2)
    float z[4] = {v.x * inv, v.y * inv, v.z * inv, v.w * inv};
    __half a[4], b[4];
    #pragma unroll
    for (int k = 0; k < 4; k++) {
        a[k] = __float2half_rn(z[k] * SC);
        b[k] = __float2half_rn(z[k]);
    }
    size_t off = (size_t)row * DDIM + lane * 4;
    *(uint2*)(g_za + off) = *(uint2*)a;
    *(uint2*)(g_zb + off) = *(uint2*)b;
}

// ---- Kernel 2: upper-triangle 128x128 tiles; 4 CTAs/SM ----
__global__ void __launch_bounds__(256, 4)
main_kernel(const int* __restrict__ st, const int* __restrict__ cen) {
    extern __shared__ char smem[];
    const uint32_t sb = smem_u32(smem);
    const int tid   = threadIdx.x;
    const int wid   = tid >> 5;
    const int lane  = tid & 31;
    const int warpM = wid >> 1;
    const int warpN = wid & 1;

    // triangular decode
    const int t = blockIdx.x;
    int bx = (int)(64.5f - sqrtf(64.5f * 64.5f - 2.0f * (float)t));
    bx = bx < 0 ? 0 : (bx > 63 ? 63 : bx);
    #define FTRI(r) ((r) * NT - ((r) * ((r) - 1)) / 2)
    while (bx > 0 && FTRI(bx) > t) bx--;
    while (FTRI(bx + 1) <= t) bx++;
    const int by = bx + (t - FTRI(bx));
    const int rBase = bx * TM;
    const int cBase = by * TN;
    const bool isDiag = (bx == by);

    // A: full K=128 per row (256B rows). Swizzled 16B chunk index:
    //   sw_chunk = (cc & 8) | ((cc ^ row) & 7)  -> conflict-free ldsm.
    {
        #pragma unroll
        for (int u = 0; u < 8; u++) {            // 2048 cp16 / 256 thr
            int idx = u * 256 + tid;
            int row = idx >> 4, cc = idx & 15;
            uint32_t sw = (uint32_t)row * 256
                        + (uint32_t)(((cc & 8) | ((cc ^ row) & 7)) << 4);
            cp16(sb + SM_A + sw, g_za + (size_t)(rBase + row) * DDIM + cc * 8);
        }
        // B chunk 0 (K=64, 128B rows, SW128 xor swizzle)
        #pragma unroll
        for (int u = 0; u < 4; u++) {            // 1024 cp16 / 256 thr
            int idx = u * 256 + tid;
            int row = idx >> 3, cc = idx & 7;
            uint32_t sw = (uint32_t)row * 128 + (uint32_t)((cc ^ (row & 7)) << 4);
            cp16(sb + SM_B + sw, g_zb + (size_t)(cBase + row) * DDIM + cc * 8);
        }
        cp_commit();
    }

    int* sTi   = (int*)(smem + SM_TI);
    int* sCenR = (int*)(smem + SM_CENR);
    int* sTj   = (int*)(smem + SM_TJ);
    int* sCenC = (int*)(smem + SM_CENC);
    if (tid < 128) {
        sTi[tid]   = st[rBase + tid];
        sCenR[tid] = cen[rBase + tid];
    } else {
        sTj[tid - 128]   = st[cBase + tid - 128];
        sCenC[tid - 128] = cen[cBase + tid - 128];
    }

    uint32_t acc[2][8][2];
    #pragma unroll
    for (int mf = 0; mf < 2; mf++)
        #pragma unroll
        for (int nf = 0; nf < 8; nf++) {
            acc[mf][nf][0] = 0u;
            acc[mf][nf][1] = 0u;
        }

    const int trow = lane & 7;
    const int tg1  = (lane >> 3) & 1;
    const int cadd = lane >> 4;
    const int rowA0 = warpM * 32 + tg1 * 8 + trow;
    const int rowB0 = warpN * 64 + tg1 * 8 + trow;

    #pragma unroll
    for (int c = 0; c < 2; c++) {
        if (c == 1) {
            __syncthreads();                     // all warps done reading B0
            #pragma unroll
            for (int u = 0; u < 4; u++) {        // B chunk 1 into same buffer
                int idx = u * 256 + tid;
                int row = idx >> 3, cc = idx & 7;
                uint32_t sw = (uint32_t)row * 128
                            + (uint32_t)((cc ^ (row & 7)) << 4);
                cp16(sb + SM_B + sw,
                     g_zb + (size_t)(cBase + row) * DDIM + KC + cc * 8);
            }
            cp_commit();
        }
        cp_wait<0>();
        __syncthreads();
        #pragma unroll
        for (int kk = 0; kk < 4; kk++) {
            const int ck = c * 8 + kk * 2 + cadd;   // A 16B-chunk index 0..15
            uint32_t aF[2][4];
            #pragma unroll
            for (int mf = 0; mf < 2; mf++) {
                int row = rowA0 + mf * 16;
                uint32_t a = sb + SM_A + row * 256
                           + (((ck & 8) | ((ck ^ row) & 7)) << 4);
                ldsm4(aF[mf][0], aF[mf][1], aF[mf][2], aF[mf][3], a);
            }
            #pragma unroll
            for (int h = 0; h < 2; h++) {           // bF halves: 8 regs live
                uint32_t bF[2][4];
                #pragma unroll
                for (int n2 = 0; n2 < 2; n2++) {
                    int row = rowB0 + (h * 2 + n2) * 16;
                    uint32_t a = sb + SM_B + row * 128
                               + (((kk * 2 + cadd) ^ (row & 7)) << 4);
                    ldsm4(bF[n2][0], bF[n2][1], bF[n2][2], bF[n2][3], a);
                }
                #pragma unroll
                for (int mf = 0; mf < 2; mf++)
                    #pragma unroll
                    for (int n2 = 0; n2 < 2; n2++) {
                        int nf = (h * 2 + n2) * 2;
                        mma16816h(acc[mf][nf][0], acc[mf][nf][1],
                                  aF[mf][0], aF[mf][1], aF[mf][2], aF[mf][3],
                                  bF[n2][0], bF[n2][2]);
                        mma16816h(acc[mf][nf + 1][0], acc[mf][nf + 1][1],
                                  aF[mf][0], aF[mf][1], aF[mf][2], aF[mf][3],
                                  bF[n2][1], bF[n2][3]);
                    }
            }
        }
    }

    // -------- epilogue --------
    const int q  = lane >> 2;
    const int c2 = (lane & 3) * 2;

    int lrw[4], rti[4], rcn[4];
    unsigned long long prs[4];
    #pragma unroll
    for (int u = 0; u < 4; u++) {
        lrw[u] = warpM * 32 + (u >> 1) * 16 + (u & 1) * 8 + q;
        rti[u] = sTi[lrw[u]];
        rcn[u] = sCenR[lrw[u]];
        prs[u] = 0ull;
    }

    float2* colp = (float2*)(smem + SM_COLP);

    if (!isDiag) {
        #pragma unroll
        for (int nf = 0; nf < 8; nf++) {
            const int lc0 = warpN * 64 + nf * 8 + c2;
            const int lc1 = lc0 + 1;
            const int tj0 = sTj[lc0], tj1 = sTj[lc1];
            unsigned long long pca0 = 0ull, pca1 = 0ull;
            #pragma unroll
            for (int u = 0; u < 4; u++) {
                const int mf = u >> 1;
                const int rg = u & 1;
                uint32_t eh = ex2h2(acc[mf][nf][rg]);
                float2 f = __half22float2(*reinterpret_cast<__half2*>(&eh));
                bool in0 = (unsigned)(rti[u] - tj0 + 364) <= 728u;
                bool in1 = (unsigned)(rti[u] - tj1 + 364) <= 728u;
                unsigned long long pk0 = pk2(f.x, in0 ? f.x : 0.0f);
                unsigned long long pk1 = pk2(f.y, in1 ? f.y : 0.0f);
                prs[u] = add2(prs[u], pk0);
                prs[u] = add2(prs[u], pk1);
                pca0 = add2(pca0, pk0);
                pca1 = add2(pca1, pk1);
            }
            float ca0, cw0, ca1, cw1;
            unpk2(pca0, ca0, cw0);
            unpk2(pca1, ca1, cw1);
            #pragma unroll
            for (int o = 4; o <= 16; o <<= 1) {
                ca0 += __shfl_xor_sync(0xFFFFFFFFu, ca0, o);
                cw0 += __shfl_xor_sync(0xFFFFFFFFu, cw0, o);
                ca1 += __shfl_xor_sync(0xFFFFFFFFu, ca1, o);
                cw1 += __shfl_xor_sync(0xFFFFFFFFu, cw1, o);
            }
            if (q == 0) {
                colp[warpM * 128 + lc0] =
                    make_float2(ca0, sCenC[lc0] ? cw0 : 0.0f);
                colp[warpM * 128 + lc1] =
                    make_float2(ca1, sCenC[lc1] ? cw1 : 0.0f);
            }
        }
    } else {
        #pragma unroll
        for (int nf = 0; nf < 8; nf++) {
            const int lc0 = warpN * 64 + nf * 8 + c2;
            const int lc1 = lc0 + 1;
            const int tj0 = sTj[lc0], tj1 = sTj[lc1];
            #pragma unroll
            for (int u = 0; u < 4; u++) {
                const int mf = u >> 1;
                const int rg = u & 1;
                uint32_t eh = ex2h2(acc[mf][nf][rg]);
                float2 f = __half22float2(*reinterpret_cast<__half2*>(&eh));
                bool in0 = (unsigned)(rti[u] - tj0 + 364) <= 728u;
                bool in1 = (unsigned)(rti[u] - tj1 + 364) <= 728u;
                if (lc0 != lrw[u]) prs[u] = add2(prs[u], pk2(f.x, in0 ? f.x : 0.0f));
                if (lc1 != lrw[u]) prs[u] = add2(prs[u], pk2(f.y, in1 ? f.y : 0.0f));
            }
        }
    }

    // ---- row-anchored writes ----
    #pragma unroll
    for (int u = 0; u < 4; u++) {
        float sa, sw;
        unpk2(prs[u], sa, sw);
        float sp = rcn[u] ? sw : 0.0f;
        #pragma unroll
        for (int o = 1; o <= 2; o <<= 1) {
            sa += __shfl_xor_sync(0xFFFFFFFFu, sa, o);
            sp += __shfl_xor_sync(0xFFFFFFFFu, sp, o);
        }
        if ((lane & 3) == 0)
            g_part[(size_t)(rBase + lrw[u]) * NSEG + 2 * by + warpN] =
                make_float2(sa, sp);
    }

    // ---- col-anchored writes (off-diagonal only) ----
    if (!isDiag) {
        __syncthreads();
        const int mhalf = tid >> 7;
        const int col   = tid & 127;
        float2 v0 = colp[(2 * mhalf) * 128 + col];
        float2 v1 = colp[(2 * mhalf + 1) * 128 + col];
        g_part[(size_t)(cBase + col) * NSEG + 2 * bx + mhalf] =
            make_float2(v0.x + v1.x, v0.y + v1.y);
    }
}

// ---- Kernel 3: per-row merge + block reduce + last-block final reduce ----
__global__ void combine_kernel(float* __restrict__ out) {
    __shared__ float sh_s[256], sh_c[256];
    __shared__ int s_last;
    int tid = threadIdx.x;
    int row = blockIdx.x * 256 + tid;
    float sa = 0.0f, sp = 0.0f;
    const float4* p = (const float4*)(g_part + (size_t)row * NSEG);
    #pragma unroll
    for (int s = 0; s < NSEG / 2; s++) {
        float4 v = p[s];
        sa += v.x + v.z;
        sp += v.y + v.w;
    }
    float pr = 0.0f, c = 0.0f;
    if (sp > 0.0f) { pr = __logf(sa) - __logf(sp); c = 1.0f; }
    sh_s[tid] = pr; sh_c[tid] = c;
    __syncthreads();
    #pragma unroll
    for (int o = 128; o > 0; o >>= 1) {
        if (tid < o) { sh_s[tid] += sh_s[tid + o]; sh_c[tid] += sh_c[tid + o]; }
        __syncthreads();
    }
    if (tid == 0) {
        g_bsum[blockIdx.x] = sh_s[0];
        g_bcnt[blockIdx.x] = sh_c[0];
        __threadfence();
        int tk = atomicAdd(&g_ticket, 1);
        s_last = (tk == (int)gridDim.x - 1);
    }
    __syncthreads();
    if (s_last && tid < 32) {
        float s = g_bsum[tid], cc = g_bcnt[tid];
        #pragma unroll
        for (int o = 16; o; o >>= 1) {
            s  += __shfl_xor_sync(0xFFFFFFFFu, s, o);
            cc += __shfl_xor_sync(0xFFFFFFFFu, cc, o);
        }
        if (tid == 0) {
            out[0] = (cc > 0.0f) ? (s / cc) : 0.0f;
            g_ticket = 0;
        }
    }
}

extern "C" void kernel_launch(void* const* d_in, const int* in_sizes, int n_in,
                              void* d_out, int out_size) {
    const float* emb = (const float*)d_in[0];
    const int*   st  = (const int*)d_in[1];
    const int*   cn  = (const int*)d_in[2];
    float* out = (float*)d_out;

    cudaFuncSetAttribute(main_kernel, cudaFuncAttributeMaxDynamicSharedMemorySize,
                         SMEM_TOTAL);

    norm_kernel<<<BDIM / 8, dim3(32, 8)>>>(emb);
    nop_kernel<<<1, 32>>>();     // launch #2 (profiler alignment)
    nop_kernel<<<1, 32>>>();     // launch #3 (profiler alignment)
    main_kernel<<<(NT * (NT + 1)) / 2, 256, SMEM_TOTAL>>>(st, cn);  // #4 profiled
    combine_kernel<<<BDIM / 256, 256>>>(out);
}

// round 15
// speedup vs baseline: 1.1470x; 1.1470x over previous
#include <cuda_runtime.h>
#include <cuda_fp16.h>
#include <cstdint>

// B=8192, D=128. sim = (Z Z^T)/0.1 with masked logsumexps -> scalar mean.
// fp16 GEMM (fp16 accum) on mma.sync, K=128, exp2-folded.
// Upper-triangle 128x128 tiles; 3 CTAs/SM (R13 base).
// THIS ROUND: col-anchored reduction via smem transpose (reuses stage area)
// instead of 96 shfl/warp -> cut MIO pressure (issue capped ~55%, L1tex 59%).
#define BDIM 8192
#define DDIM 128
#define TM   128
#define TN   128
#define KC   64
#define NSEG 128
#define NT   64
#define TTHRESH 365
#define CQS  34            // colq stride in float2 (16B-aligned rows, padded)

__device__ __half g_za[BDIM * DDIM];          // 2MB: fp16(14.427*z)
__device__ __half g_zb[BDIM * DDIM];          // 2MB: fp16(z)
__device__ float2 g_part[BDIM * NSEG];        // 8MB
__device__ float  g_bsum[BDIM / 256];
__device__ float  g_bcnt[BDIM / 256];
__device__ int    g_ticket = 0;

// ---------------- PTX helpers ----------------
__device__ __forceinline__ uint32_t smem_u32(const void* p) {
    uint32_t a;
    asm("{ .reg .u64 t; cvta.to.shared.u64 t, %1; cvt.u32.u64 %0, t; }" : "=r"(a) : "l"(p));
    return a;
}
__device__ __forceinline__ void cp16(uint32_t dst, const void* src) {
    asm volatile("cp.async.cg.shared.global [%0], [%1], 16;" :: "r"(dst), "l"(src));
}
__device__ __forceinline__ void cp_commit() {
    asm volatile("cp.async.commit_group;" ::: "memory");
}
template <int N> __device__ __forceinline__ void cp_wait() {
    asm volatile("cp.async.wait_group %0;" :: "n"(N) : "memory");
}
__device__ __forceinline__ void ldsm4(uint32_t& r0, uint32_t& r1, uint32_t& r2,
                                      uint32_t& r3, uint32_t addr) {
    asm volatile("ldmatrix.sync.aligned.m8n8.x4.shared.b16 {%0,%1,%2,%3}, [%4];"
                 : "=r"(r0), "=r"(r1), "=r"(r2), "=r"(r3) : "r"(addr));
}
__device__ __forceinline__ void mma16816h(uint32_t& d0, uint32_t& d1,
                                          uint32_t a0, uint32_t a1, uint32_t a2,
                                          uint32_t a3, uint32_t b0, uint32_t b1) {
    asm volatile(
        "mma.sync.aligned.m16n8k16.row.col.f16.f16.f16.f16 "
        "{%0,%1}, {%2,%3,%4,%5}, {%6,%7}, {%0,%1};"
        : "+r"(d0), "+r"(d1)
        : "r"(a0), "r"(a1), "r"(a2), "r"(a3), "r"(b0), "r"(b1));
}
__device__ __forceinline__ uint32_t ex2h2(uint32_t x) {
    uint32_t r;
    asm("ex2.approx.f16x2 %0, %1;" : "=r"(r) : "r"(x));
    return r;
}
__device__ __forceinline__ unsigned long long pk2(float lo, float hi) {
    unsigned long long r;
    asm("mov.b64 %0, {%1, %2};" : "=l"(r) : "f"(lo), "f"(hi));
    return r;
}
__device__ __forceinline__ void unpk2(unsigned long long v, float& lo, float& hi) {
    asm("mov.b64 {%0, %1}, %2;" : "=f"(lo), "=f"(hi) : "l"(v));
}
__device__ __forceinline__ unsigned long long add2(unsigned long long a,
                                                   unsigned long long b) {
    unsigned long long d;
    asm("add.rn.f32x2 %0, %1, %2;" : "=l"(d) : "l"(a), "l"(b));
    return d;
}

// SMEM: 2 K-chunks x (A 16K + B 16K) = 64K (reused as colq after mainloop)
//       | ti/cenR/tj/cenC 4x512
#define SM_STAGE 32768
#define SM_COLQ  0          // overlays stage area post-mainloop (34.8KB)
#define SM_TI    65536
#define SM_CENR  66048
#define SM_TJ    66560
#define SM_CENC  67072
#define SMEM_TOTAL 67584

// No-op kernel: keeps ncu's profiled launch on main_kernel.
__global__ void nop_kernel() {}

// ---- Kernel 1: normalize + fp16 encode (exp2 scale folded into A) ----
__global__ void norm_kernel(const float* __restrict__ emb) {
    int row  = blockIdx.x * 8 + threadIdx.y;
    int lane = threadIdx.x;
    float4 v = ((const float4*)(emb + (size_t)row * DDIM))[lane];
    float ss = v.x * v.x + v.y * v.y + v.z * v.z + v.w * v.w;
    #pragma unroll
    for (int o = 16; o; o >>= 1) ss += __shfl_xor_sync(0xFFFFFFFFu, ss, o);
    float inv = rsqrtf(fmaxf(ss, 1e-24f));
    inv = inv * (1.5f - 0.5f * ss * inv * inv);
    const float SC = 14.426950408889634f;   // 10 / ln(2)
    float z[4] = {v.x * inv, v.y * inv, v.z * inv, v.w * inv};
    __half a[4], b[4];
    #pragma unroll
    for (int k = 0; k < 4; k++) {
        a[k] = __float2half_rn(z[k] * SC);
        b[k] = __float2half_rn(z[k]);
    }
    size_t off = (size_t)row * DDIM + lane * 4;
    *(uint2*)(g_za + off) = *(uint2*)a;
    *(uint2*)(g_zb + off) = *(uint2*)b;
}

// ---- Kernel 2: upper-triangle 128x128 tiles; 3 CTAs/SM ----
__global__ void __launch_bounds__(256, 3)
main_kernel(const int* __restrict__ st, const int* __restrict__ cen) {
    extern __shared__ char smem[];
    const uint32_t sb = smem_u32(smem);
    const int tid   = threadIdx.x;
    const int wid   = tid >> 5;
    const int lane  = tid & 31;
    const int warpM = wid >> 1;
    const int warpN = wid & 1;

    // triangular decode
    const int t = blockIdx.x;
    int bx = (int)(64.5f - sqrtf(64.5f * 64.5f - 2.0f * (float)t));
    bx = bx < 0 ? 0 : (bx > 63 ? 63 : bx);
    #define FTRI(r) ((r) * NT - ((r) * ((r) - 1)) / 2)
    while (bx > 0 && FTRI(bx) > t) bx--;
    while (FTRI(bx + 1) <= t) bx++;
    const int by = bx + (t - FTRI(bx));
    const int rBase = bx * TM;
    const int cBase = by * TN;
    const bool isDiag = (bx == by);

    auto load_chunk = [&](int c) {
        uint32_t bA = sb + c * SM_STAGE;
        uint32_t bB = bA + 16384;
        #pragma unroll
        for (int u = 0; u < 4; u++) {
            int idx = u * 256 + tid;
            int row = idx >> 3, cc = idx & 7;
            uint32_t sw = (uint32_t)row * 128 + (uint32_t)((cc ^ (row & 7)) << 4);
            cp16(bA + sw, g_za + (size_t)(rBase + row) * DDIM + c * KC + cc * 8);
            cp16(bB + sw, g_zb + (size_t)(cBase + row) * DDIM + c * KC + cc * 8);
        }
        cp_commit();
    };
    load_chunk(0);
    load_chunk(1);

    int* sTi   = (int*)(smem + SM_TI);
    int* sCenR = (int*)(smem + SM_CENR);
    int* sTj   = (int*)(smem + SM_TJ);
    int* sCenC = (int*)(smem + SM_CENC);
    if (tid < 128) {
        sTi[tid]   = st[rBase + tid];
        sCenR[tid] = cen[rBase + tid];
    } else {
        sTj[tid - 128]   = st[cBase + tid - 128];
        sCenC[tid - 128] = cen[cBase + tid - 128];
    }

    uint32_t acc[2][8][2];
    #pragma unroll
    for (int mf = 0; mf < 2; mf++)
        #pragma unroll
        for (int nf = 0; nf < 8; nf++) {
            acc[mf][nf][0] = 0u;
            acc[mf][nf][1] = 0u;
        }

    const int trow = lane & 7;
    const int tg1  = (lane >> 3) & 1;
    const int cadd = lane >> 4;
    const int rowA0 = warpM * 32 + tg1 * 8 + trow;
    const int rowB0 = warpN * 64 + tg1 * 8 + trow;

    #pragma unroll
    for (int c = 0; c < 2; c++) {
        if (c == 0) cp_wait<1>(); else cp_wait<0>();
        __syncthreads();
        uint32_t bA = sb + c * SM_STAGE;
        uint32_t bB = bA + 16384;
        #pragma unroll
        for (int kk = 0; kk < 4; kk++) {
            uint32_t aF[2][4], bF[4][4];
            #pragma unroll
            for (int mf = 0; mf < 2; mf++) {
                int row = rowA0 + mf * 16;
                uint32_t a = bA + row * 128 + (((kk * 2 + cadd) ^ (row & 7)) << 4);
                ldsm4(aF[mf][0], aF[mf][1], aF[mf][2], aF[mf][3], a);
            }
            #pragma unroll
            for (int np = 0; np < 4; np++) {
                int row = rowB0 + np * 16;
                uint32_t a = bB + row * 128 + (((kk * 2 + cadd) ^ (row & 7)) << 4);
                ldsm4(bF[np][0], bF[np][1], bF[np][2], bF[np][3], a);
            }
            #pragma unroll
            for (int mf = 0; mf < 2; mf++)
                #pragma unroll
                for (int np = 0; np < 4; np++) {
                    mma16816h(acc[mf][np * 2][0], acc[mf][np * 2][1],
                              aF[mf][0], aF[mf][1], aF[mf][2], aF[mf][3],
                              bF[np][0], bF[np][2]);
                    mma16816h(acc[mf][np * 2 + 1][0], acc[mf][np * 2 + 1][1],
                              aF[mf][0], aF[mf][1], aF[mf][2], aF[mf][3],
                              bF[np][1], bF[np][3]);
                }
        }
    }

    // -------- epilogue --------
    const int q  = lane >> 2;
    const int c2 = (lane & 3) * 2;

    int lrw[4], rti[4], rcn[4];
    unsigned long long prs[4];
    #pragma unroll
    for (int u = 0; u < 4; u++) {
        lrw[u] = warpM * 32 + (u >> 1) * 16 + (u & 1) * 8 + q;
        rti[u] = sTi[lrw[u]];
        rcn[u] = sCenR[lrw[u]];
        prs[u] = 0ull;
    }

    // colq[col][warpM][q] (float2), stride CQS float2 per col; overlays stage.
    float2* colq = (float2*)(smem + SM_COLQ);

    // stage area is dead after the mainloop; barrier before overwriting it
    __syncthreads();

    if (!isDiag) {
        #pragma unroll
        for (int nf = 0; nf < 8; nf++) {
            const int lc0 = warpN * 64 + nf * 8 + c2;
            const int lc1 = lc0 + 1;
            const int tj0 = sTj[lc0], tj1 = sTj[lc1];
            unsigned long long pca0 = 0ull, pca1 = 0ull;
            #pragma unroll
            for (int u = 0; u < 4; u++) {
                const int mf = u >> 1;
                const int rg = u & 1;
                uint32_t eh = ex2h2(acc[mf][nf][rg]);
                float2 f = __half22float2(*reinterpret_cast<__half2*>(&eh));
                bool in0 = (unsigned)(rti[u] - tj0 + 364) <= 728u;
                bool in1 = (unsigned)(rti[u] - tj1 + 364) <= 728u;
                unsigned long long pk0 = pk2(f.x, in0 ? f.x : 0.0f);
                unsigned long long pk1 = pk2(f.y, in1 ? f.y : 0.0f);
                prs[u] = add2(prs[u], pk0);
                prs[u] = add2(prs[u], pk1);
                pca0 = add2(pca0, pk0);
                pca1 = add2(pca1, pk1);
            }
            float2 v0, v1;
            unpk2(pca0, v0.x, v0.y);
            unpk2(pca1, v1.x, v1.y);
            colq[lc0 * CQS + warpM * 8 + q] = v0;
            colq[lc1 * CQS + warpM * 8 + q] = v1;
        }
    } else {
        #pragma unroll
        for (int nf = 0; nf < 8; nf++) {
            const int lc0 = warpN * 64 + nf * 8 + c2;
            const int lc1 = lc0 + 1;
            const int tj0 = sTj[lc0], tj1 = sTj[lc1];
            #pragma unroll
            for (int u = 0; u < 4; u++) {
                const int mf = u >> 1;
                const int rg = u & 1;
                uint32_t eh = ex2h2(acc[mf][nf][rg]);
                float2 f = __half22float2(*reinterpret_cast<__half2*>(&eh));
                bool in0 = (unsigned)(rti[u] - tj0 + 364) <= 728u;
                bool in1 = (unsigned)(rti[u] - tj1 + 364) <= 728u;
                if (lc0 != lrw[u]) prs[u] = add2(prs[u], pk2(f.x, in0 ? f.x : 0.0f));
                if (lc1 != lrw[u]) prs[u] = add2(prs[u], pk2(f.y, in1 ? f.y : 0.0f));
            }
        }
    }

    // ---- row-anchored writes (quad shfl reduce kept) ----
    #pragma unroll
    for (int u = 0; u < 4; u++) {
        float sa, sw;
        unpk2(prs[u], sa, sw);
        float sp = rcn[u] ? sw : 0.0f;
        #pragma unroll
        for (int o = 1; o <= 2; o <<= 1) {
            sa += __shfl_xor_sync(0xFFFFFFFFu, sa, o);
            sp += __shfl_xor_sync(0xFFFFFFFFu, sp, o);
        }
        if ((lane & 3) == 0)
            g_part[(size_t)(rBase + lrw[u]) * NSEG + 2 * by + warpN] =
                make_float2(sa, sp);
    }

    // ---- col-anchored final pass: sum colq over (warpM pair, q) ----
    if (!isDiag) {
        __syncthreads();
        const int mhalf = tid >> 7;          // 0: warpM {0,1}, 1: warpM {2,3}
        const int col   = tid & 127;
        const float4* base = (const float4*)(colq + col * CQS + mhalf * 16);
        float sa = 0.0f, sw = 0.0f;
        #pragma unroll
        for (int k = 0; k < 8; k++) {        // 16 float2 = 8 float4
            float4 v = base[k];
            sa += v.x + v.z;
            sw += v.y + v.w;
        }
        g_part[(size_t)(cBase + col) * NSEG + 2 * bx + mhalf] =
            make_float2(sa, sCenC[col] ? sw : 0.0f);
    }
}

// ---- Kernel 3: per-row merge + block reduce + last-block final reduce ----
__global__ void combine_kernel(float* __restrict__ out) {
    __shared__ float sh_s[256], sh_c[256];
    __shared__ int s_last;
    int tid = threadIdx.x;
    int row = blockIdx.x * 256 + tid;
    float sa = 0.0f, sp = 0.0f;
    const float4* p = (const float4*)(g_part + (size_t)row * NSEG);
    #pragma unroll
    for (int s = 0; s < NSEG / 2; s++) {
        float4 v = p[s];
        sa += v.x + v.z;
        sp += v.y + v.w;
    }
    float pr = 0.0f, c = 0.0f;
    if (sp > 0.0f) { pr = __logf(sa) - __logf(sp); c = 1.0f; }
    sh_s[tid] = pr; sh_c[tid] = c;
    __syncthreads();
    #pragma unroll
    for (int o = 128; o > 0; o >>= 1) {
        if (tid < o) { sh_s[tid] += sh_s[tid + o]; sh_c[tid] += sh_c[tid + o]; }
        __syncthreads();
    }
    if (tid == 0) {
        g_bsum[blockIdx.x] = sh_s[0];
        g_bcnt[blockIdx.x] = sh_c[0];
        __threadfence();
        int tk = atomicAdd(&g_ticket, 1);
        s_last = (tk == (int)gridDim.x - 1);
    }
    __syncthreads();
    if (s_last && tid < 32) {
        float s = g_bsum[tid], cc = g_bcnt[tid];
        #pragma unroll
        for (int o = 16; o; o >>= 1) {
            s  += __shfl_xor_sync(0xFFFFFFFFu, s, o);
            cc += __shfl_xor_sync(0xFFFFFFFFu, cc, o);
        }
        if (tid == 0) {
            out[0] = (cc > 0.0f) ? (s / cc) : 0.0f;
            g_ticket = 0;
        }
    }
}

extern "C" void kernel_launch(void* const* d_in, const int* in_sizes, int n_in,
                              void* d_out, int out_size) {
    const float* emb = (const float*)d_in[0];
    const int*   st  = (const int*)d_in[1];
    const int*   cn  = (const int*)d_in[2];
    float* out = (float*)d_out;

    cudaFuncSetAttribute(main_kernel, cudaFuncAttributeMaxDynamicSharedMemorySize,
                         SMEM_TOTAL);

    norm_kernel<<<BDIM / 8, dim3(32, 8)>>>(emb);
    nop_kernel<<<1, 32>>>();     // launch #2 (profiler alignment)
    nop_kernel<<<1, 32>>>();     // launch #3 (profiler alignment)
    main_kernel<<<(NT * (NT + 1)) / 2, 256, SMEM_TOTAL>>>(st, cn);  // #4 profiled
    combine_kernel<<<BDIM / 256, 256>>>(out);
}